// round 16
// baseline (speedup 1.0000x reference)
#include <cuda_runtime.h>
#include <cuda_bf16.h>
#include <cstdint>

#define BT   8192
#define TT   2048
#define NB   4
#define Dm   2048
#define KD   1024
#define VD   2048

// ---------------- scratch (device globals; allocation-free rule) -----------
__device__ __align__(128) float g_x[BT * Dm];     // normalized input (fp32)
__device__ __align__(128) float g_k[BT * KD];     // ktilde fp32 [b][t][n]
__device__ __align__(128) float g_v[BT * VD];     // v      fp32 [b][t][n]
__device__ __align__(128) float g_e[BT * KD];     // ls, then e = exp(suffix sum)
__device__ __align__(128) float g_g1[BT * 16];
__device__ __align__(128) float g_csum[NB * KD * 32];
__device__ __align__(128) float g_gtot[NB * KD];

// ---------------- helpers (NO ldmatrix, NO cp.async anywhere) ---------------
__device__ __forceinline__ void mma_bf16(float* d, const uint32_t* a, uint32_t b0, uint32_t b1) {
    asm volatile("mma.sync.aligned.m16n8k16.row.col.f32.bf16.bf16.f32 "
                 "{%0,%1,%2,%3}, {%4,%5,%6,%7}, {%8,%9}, {%0,%1,%2,%3};"
                 : "+f"(d[0]), "+f"(d[1]), "+f"(d[2]), "+f"(d[3])
                 : "r"(a[0]), "r"(a[1]), "r"(a[2]), "r"(a[3]), "r"(b0), "r"(b1));
}
__device__ __forceinline__ uint32_t pack_bf2(float a, float b) {
    __nv_bfloat162 t = __floats2bfloat162_rn(a, b);  // .x=a (low), .y=b (high)
    return *(uint32_t*)&t;
}

// ---------------------------------------------------------------------------
// Kernel 1: RMSNorm (proven) -> fp32 g_x, plus g1 = x @ Wg1
// ---------------------------------------------------------------------------
__global__ __launch_bounds__(256) void k_rmsnorm(const float* __restrict__ seg,
                                                 const float* __restrict__ nw,
                                                 const float* __restrict__ Wg1) {
    int row = blockIdx.x;
    int tid = threadIdx.x;
    const float4* s4 = (const float4*)(seg + (size_t)row * Dm);
    float4 v0 = s4[tid];
    float4 v1 = s4[tid + 256];
    float ss = v0.x*v0.x + v0.y*v0.y + v0.z*v0.z + v0.w*v0.w
             + v1.x*v1.x + v1.y*v1.y + v1.z*v1.z + v1.w*v1.w;
    #pragma unroll
    for (int o = 16; o; o >>= 1) ss += __shfl_xor_sync(0xffffffffu, ss, o);
    __shared__ float sred[8];
    int wid = tid >> 5, lane = tid & 31;
    if (lane == 0) sred[wid] = ss;
    __syncthreads();
    float tot = 0.f;
    #pragma unroll
    for (int w = 0; w < 8; w++) tot += sred[w];
    float rinv = rsqrtf(tot * (1.0f / Dm) + 1e-5f);

    const float4* w4 = (const float4*)nw;
    float4 n0 = w4[tid], n1 = w4[tid + 256];
    float4 x0, x1;
    x0.x = v0.x*rinv*n0.x; x0.y = v0.y*rinv*n0.y; x0.z = v0.z*rinv*n0.z; x0.w = v0.w*rinv*n0.w;
    x1.x = v1.x*rinv*n1.x; x1.y = v1.y*rinv*n1.y; x1.z = v1.z*rinv*n1.z; x1.w = v1.w*rinv*n1.w;
    float4* xo = (float4*)(g_x + (size_t)row * Dm);
    xo[tid] = x0;
    xo[tid + 256] = x1;

    float p[16];
    #pragma unroll
    for (int j = 0; j < 16; j++) p[j] = 0.f;
    float xa[4] = {x0.x, x0.y, x0.z, x0.w};
    float xb[4] = {x1.x, x1.y, x1.z, x1.w};
    #pragma unroll
    for (int i = 0; i < 4; i++) {
        const float* wg = Wg1 + (size_t)(tid * 4 + i) * 16;
        #pragma unroll
        for (int j = 0; j < 16; j++) p[j] += xa[i] * wg[j];
    }
    #pragma unroll
    for (int i = 0; i < 4; i++) {
        const float* wg = Wg1 + (size_t)(1024 + tid * 4 + i) * 16;
        #pragma unroll
        for (int j = 0; j < 16; j++) p[j] += xb[i] * wg[j];
    }
    #pragma unroll
    for (int o = 16; o; o >>= 1) {
        #pragma unroll
        for (int j = 0; j < 16; j++) p[j] += __shfl_xor_sync(0xffffffffu, p[j], o);
    }
    __shared__ float pg[8][16];
    if (lane == 0) {
        #pragma unroll
        for (int j = 0; j < 16; j++) pg[wid][j] = p[j];
    }
    __syncthreads();
    if (tid < 16) {
        float s = 0.f;
        #pragma unroll
        for (int w = 0; w < 8; w++) s += pg[w][tid];
        g_g1[row * 16 + tid] = s;
    }
}

// ---------------------------------------------------------------------------
// Gate phase 1 (proven round-8): ls -> g_e; chunk sums -> g_csum
// ---------------------------------------------------------------------------
__global__ __launch_bounds__(256) void k_gate1(const float* __restrict__ Wg2,
                                               const float* __restrict__ bg2) {
    int blk = blockIdx.x;
    int b = blk >> 5, tc = blk & 31, t0 = tc * 64;
    int tid = threadIdx.x;
    __shared__ __align__(16) float sh[64 * 16];
    ((float4*)sh)[tid] = ((const float4*)(g_g1 + ((size_t)b * TT + t0) * 16))[tid];
    __syncthreads();
    float w[4][16], bias[4], cs[4] = {0.f, 0.f, 0.f, 0.f};
    #pragma unroll
    for (int cc = 0; cc < 4; cc++) {
        int col = cc * 256 + tid;
        #pragma unroll
        for (int j = 0; j < 16; j++) w[cc][j] = Wg2[j * KD + col];
        bias[cc] = bg2[col];
    }
    for (int t = 0; t < 64; t++) {
        const float* g1r = sh + t * 16;
        float* er = g_e + ((size_t)b * TT + t0 + t) * KD;
        #pragma unroll
        for (int cc = 0; cc < 4; cc++) {
            float z = bias[cc];
            #pragma unroll
            for (int j = 0; j < 16; j++) z += g1r[j] * w[cc][j];
            float ls = (fminf(z, 0.f) - log1pf(__expf(-fabsf(z)))) * 0.0625f;
            cs[cc] += ls;
            er[cc * 256 + tid] = ls;
        }
    }
    #pragma unroll
    for (int cc = 0; cc < 4; cc++)
        g_csum[((size_t)b * KD + cc * 256 + tid) * 32 + tc] = cs[cc];
}

// Gate phase 2 (proven): totals -> g_gtot
__global__ __launch_bounds__(256) void k_gate2() {
    int i = blockIdx.x * 256 + threadIdx.x;
    float s = 0.f;
    #pragma unroll
    for (int j = 0; j < 32; j++) s += g_csum[(size_t)i * 32 + j];
    g_gtot[i] = s;
}

// Gate phase 3 (proven): in-place e = exp(suffix-sum of ls)
__global__ __launch_bounds__(256) void k_gate3() {
    int blk = blockIdx.x;
    int b = blk >> 5, tc = blk & 31, t0 = tc * 64;
    int tid = threadIdx.x;
    float suf[4];
    #pragma unroll
    for (int cc = 0; cc < 4; cc++) {
        int col = cc * 256 + tid;
        const float* cp = &g_csum[((size_t)b * KD + col) * 32];
        float s = 0.f;
        for (int j = tc + 1; j < 32; j++) s += cp[j];
        suf[cc] = s;
    }
    for (int t = 63; t >= 0; t--) {
        float* er = g_e + ((size_t)b * TT + t0 + t) * KD;
        #pragma unroll
        for (int cc = 0; cc < 4; cc++) {
            float ls = er[cc * 256 + tid];
            er[cc * 256 + tid] = expf(suf[cc]);
            suf[cc] += ls;
        }
    }
}

// ---------------------------------------------------------------------------
// Kernel 3: projection GEMM — round-6 PROVEN no-ldmatrix version.
// mma.sync bf16 3-term split; fragments assembled via plain 4B smem loads.
// CTA 128x128, BK=16, 8 warps (64x32). Per-array __align__(16).
// WHICH==0 epilogue multiplies by precomputed g_e.
// ---------------------------------------------------------------------------
#define AST 18

template <int WHICH>
__global__ __launch_bounds__(256, 2) void k_mm(const float* __restrict__ W) {
    constexpr int N = WHICH ? VD : KD;
    __shared__ __align__(16) __nv_bfloat16 As_h[128 * AST];
    __shared__ __align__(16) __nv_bfloat16 As_l[128 * AST];
    __shared__ __align__(16) __nv_bfloat16 Bs_h[128 * AST];
    __shared__ __align__(16) __nv_bfloat16 Bs_l[128 * AST];
    const int tid = threadIdx.x, lane = tid & 31, wid = tid >> 5;
    const int wm = wid >> 2, wn = wid & 3;
    const int n0 = blockIdx.x * 128, m0 = blockIdx.y * 128;

    const float* A = g_x + (size_t)m0 * Dm;
    const float* B = W + n0;   // W[k][n] row-major

    float acc[4][4][4];
    #pragma unroll
    for (int i = 0; i < 4; i++)
        #pragma unroll
        for (int j = 0; j < 4; j++)
            #pragma unroll
            for (int q = 0; q < 4; q++) acc[i][j][q] = 0.f;

    const int arow = tid >> 1, ahalf = tid & 1;      // A: 128 rows x 16 k (8 fl/thr)
    const int bkk = tid >> 4, bc = (tid & 15) * 8;   // B: 16 k-rows x 128 n (8 fl/thr)
    float4 ra0, ra1, rb0, rb1;

    auto gload = [&](int k0) {
        const float4* ap = (const float4*)(A + (size_t)arow * Dm + k0 + ahalf * 8);
        ra0 = ap[0]; ra1 = ap[1];
        const float4* bp = (const float4*)(B + (size_t)(k0 + bkk) * N + bc);
        rb0 = bp[0]; rb1 = bp[1];
    };
    auto sstore = [&]() {
        int ab = arow * AST + ahalf * 8;
        float af[8] = {ra0.x, ra0.y, ra0.z, ra0.w, ra1.x, ra1.y, ra1.z, ra1.w};
        #pragma unroll
        for (int q = 0; q < 4; q++) {
            float f0 = af[q * 2], f1 = af[q * 2 + 1];
            float h0 = __bfloat162float(__float2bfloat16(f0));
            float h1 = __bfloat162float(__float2bfloat16(f1));
            *(uint32_t*)&As_h[ab + q * 2] = pack_bf2(f0, f1);
            *(uint32_t*)&As_l[ab + q * 2] = pack_bf2(f0 - h0, f1 - h1);
        }
        float bf[8] = {rb0.x, rb0.y, rb0.z, rb0.w, rb1.x, rb1.y, rb1.z, rb1.w};
        #pragma unroll
        for (int j = 0; j < 8; j++) {
            float f = bf[j];
            __nv_bfloat16 h = __float2bfloat16(f);
            Bs_h[(bc + j) * AST + bkk] = h;
            Bs_l[(bc + j) * AST + bkk] = __float2bfloat16(f - __bfloat162float(h));
        }
    };

    const int r = lane >> 2, c2 = (lane & 3) * 2;

    gload(0);
    for (int k0 = 0; k0 < Dm; k0 += 16) {
        __syncthreads();
        sstore();
        __syncthreads();
        if (k0 + 16 < Dm) gload(k0 + 16);

        uint32_t ah[4][4], al[4][4], bh[4][2], bl[4][2];
        #pragma unroll
        for (int mi = 0; mi < 4; mi++) {
            int mrow = wm * 64 + mi * 16 + r;
            ah[mi][0] = *(uint32_t*)&As_h[mrow * AST + c2];
            ah[mi][1] = *(uint32_t*)&As_h[(mrow + 8) * AST + c2];
            ah[mi][2] = *(uint32_t*)&As_h[mrow * AST + c2 + 8];
            ah[mi][3] = *(uint32_t*)&As_h[(mrow + 8) * AST + c2 + 8];
            al[mi][0] = *(uint32_t*)&As_l[mrow * AST + c2];
            al[mi][1] = *(uint32_t*)&As_l[(mrow + 8) * AST + c2];
            al[mi][2] = *(uint32_t*)&As_l[mrow * AST + c2 + 8];
            al[mi][3] = *(uint32_t*)&As_l[(mrow + 8) * AST + c2 + 8];
        }
        #pragma unroll
        for (int nj = 0; nj < 4; nj++) {
            int nrow = wn * 32 + nj * 8 + r;
            bh[nj][0] = *(uint32_t*)&Bs_h[nrow * AST + c2];
            bh[nj][1] = *(uint32_t*)&Bs_h[nrow * AST + c2 + 8];
            bl[nj][0] = *(uint32_t*)&Bs_l[nrow * AST + c2];
            bl[nj][1] = *(uint32_t*)&Bs_l[nrow * AST + c2 + 8];
        }
        #pragma unroll
        for (int mi = 0; mi < 4; mi++)
            #pragma unroll
            for (int nj = 0; nj < 4; nj++) {
                mma_bf16(acc[mi][nj], ah[mi], bh[nj][0], bh[nj][1]);
                mma_bf16(acc[mi][nj], ah[mi], bl[nj][0], bl[nj][1]);
                mma_bf16(acc[mi][nj], al[mi], bh[nj][0], bh[nj][1]);
            }
    }

    float* C = WHICH ? g_v : g_k;
    #pragma unroll
    for (int mi = 0; mi < 4; mi++) {
        int m_ = m0 + wm * 64 + mi * 16 + r;
        #pragma unroll
        for (int nj = 0; nj < 4; nj++) {
            int n_ = n0 + wn * 32 + nj * 8 + c2;
            float v0 = acc[mi][nj][0], v1 = acc[mi][nj][1];
            float v2 = acc[mi][nj][2], v3 = acc[mi][nj][3];
            if (WHICH == 0) {
                float2 e0 = *(const float2*)&g_e[(size_t)m_ * KD + n_];
                float2 e1 = *(const float2*)&g_e[(size_t)(m_ + 8) * KD + n_];
                v0 *= e0.x; v1 *= e0.y; v2 *= e1.x; v3 *= e1.y;
            }
            *(float2*)&C[(size_t)m_ * N + n_]       = make_float2(v0, v1);
            *(float2*)&C[(size_t)(m_ + 8) * N + n_] = make_float2(v2, v3);
        }
    }
}

// ---------------------------------------------------------------------------
// Kernel 4a (proven): out = initial_state * exp(Gtot)
// ---------------------------------------------------------------------------
__global__ __launch_bounds__(256) void k_init(const float* __restrict__ init,
                                              float* __restrict__ out) {
    int i = blockIdx.x * 256 + threadIdx.x;
    out[i] = init[i] * expf(g_gtot[i >> 8]);
}

// ---------------------------------------------------------------------------
// Kernel 4b (proven): S[bh] += ktilde^T @ v ; split-K atomics (fp32)
// ---------------------------------------------------------------------------
__global__ __launch_bounds__(256) void k_state(float* __restrict__ out) {
    int bh = blockIdx.y;
    int b = bh >> 3, h = bh & 7;
    int tseg0 = blockIdx.z * 256;
    __shared__ __align__(16) float As[16][128];
    __shared__ __align__(16) float Bs[16][128];
    const float* Abase = g_k + (size_t)b * TT * KD + h * 128;
    const float* Bbase = g_v + (size_t)b * TT * VD + h * 256 + blockIdx.x * 128;
    int tid = threadIdx.x;
    int tx = tid & 15, ty = tid >> 4;
    float acc[8][8];
    #pragma unroll
    for (int i = 0; i < 8; i++)
        #pragma unroll
        for (int j = 0; j < 8; j++) acc[i][j] = 0.f;

    for (int t0 = tseg0; t0 < tseg0 + 256; t0 += 16) {
        #pragma unroll
        for (int l = 0; l < 2; l++) {
            int f = tid + l * 256;
            int rr = f >> 5, cc = (f & 31) * 4;
            *(float4*)&As[rr][cc] = *(const float4*)(Abase + (size_t)(t0 + rr) * KD + cc);
            *(float4*)&Bs[rr][cc] = *(const float4*)(Bbase + (size_t)(t0 + rr) * VD + cc);
        }
        __syncthreads();
        #pragma unroll
        for (int tt = 0; tt < 16; tt++) {
            float4 a0 = *(const float4*)&As[tt][ty * 8];
            float4 a1 = *(const float4*)&As[tt][ty * 8 + 4];
            float4 b0 = *(const float4*)&Bs[tt][tx * 8];
            float4 b1 = *(const float4*)&Bs[tt][tx * 8 + 4];
            float a[8] = {a0.x, a0.y, a0.z, a0.w, a1.x, a1.y, a1.z, a1.w};
            float bb[8] = {b0.x, b0.y, b0.z, b0.w, b1.x, b1.y, b1.z, b1.w};
            #pragma unroll
            for (int i = 0; i < 8; i++)
                #pragma unroll
                for (int j = 0; j < 8; j++) acc[i][j] += a[i] * bb[j];
        }
        __syncthreads();
    }
    float* obase = out + (size_t)bh * 128 * 256 + blockIdx.x * 128;
    #pragma unroll
    for (int i = 0; i < 8; i++) {
        int kk = ty * 8 + i;
        #pragma unroll
        for (int j = 0; j < 8; j++)
            atomicAdd(&obase[(size_t)kk * 256 + tx * 8 + j], acc[i][j]);
    }
}

// ---------------------------------------------------------------------------
extern "C" void kernel_launch(void* const* d_in, const int* in_sizes, int n_in,
                              void* d_out, int out_size) {
    const float* seg  = (const float*)d_in[0];
    const float* nw   = (const float*)d_in[1];
    const float* Wk   = (const float*)d_in[2];
    const float* Wv   = (const float*)d_in[3];
    const float* Wg1  = (const float*)d_in[4];
    const float* Wg2  = (const float*)d_in[5];
    const float* bg2  = (const float*)d_in[6];
    const float* init = (const float*)d_in[7];
    float* out = (float*)d_out;

    k_rmsnorm<<<BT, 256>>>(seg, nw, Wg1);
    k_gate1<<<NB * 32, 256>>>(Wg2, bg2);
    k_gate2<<<16, 256>>>();
    k_gate3<<<NB * 32, 256>>>();
    k_mm<0><<<dim3(KD / 128, BT / 128), 256>>>(Wk);
    k_mm<1><<<dim3(VD / 128, BT / 128), 256>>>(Wv);
    k_init<<<(NB * KD * 256) / 256, 256>>>(init, out);
    k_state<<<dim3(2, 32, 8), 256>>>(out);
}